// round 11
// baseline (speedup 1.0000x reference)
#include <cuda_runtime.h>
#include <cuda_bf16.h>

#define BB 32
#define NN 512
#define CC 1024
#define HH 16
#define HD 64
#define QK_SCALE 0.125f   // 64^-0.5

// ---------------- device-global scratch (alloc-free path) --------------------
// q/k/v as bf16 hi/lo, [B,H,N,HD]; q pre-scaled by QK_SCALE
__device__ __align__(16) __nv_bfloat16 g_qh[(size_t)BB*HH*NN*HD];
__device__ __align__(16) __nv_bfloat16 g_ql[(size_t)BB*HH*NN*HD];
__device__ __align__(16) __nv_bfloat16 g_kh[(size_t)BB*HH*NN*HD];
__device__ __align__(16) __nv_bfloat16 g_kl[(size_t)BB*HH*NN*HD];
__device__ __align__(16) __nv_bfloat16 g_vh[(size_t)BB*HH*NN*HD];
__device__ __align__(16) __nv_bfloat16 g_vl[(size_t)BB*HH*NN*HD];
// input / weight splits
__device__ __align__(16) __nv_bfloat16 gx_h[(size_t)BB*NN*CC];
__device__ __align__(16) __nv_bfloat16 gx_l[(size_t)BB*NN*CC];
__device__ __align__(16) __nv_bfloat16 gwq_h[(size_t)3*CC*CC];
__device__ __align__(16) __nv_bfloat16 gwq_l[(size_t)3*CC*CC];
__device__ __align__(16) __nv_bfloat16 gwp_h[(size_t)CC*CC];
__device__ __align__(16) __nv_bfloat16 gwp_l[(size_t)CC*CC];
// attention output hi/lo [B,N,C]
__device__ __align__(16) __nv_bfloat16 go_h[(size_t)BB*NN*CC];
__device__ __align__(16) __nv_bfloat16 go_l[(size_t)BB*NN*CC];

// ---------------- baseline-ISA helpers (sm_80+) ------------------------------
__device__ __forceinline__ unsigned smem_u32(const void* p) {
    unsigned a;
    asm("{ .reg .u64 t; cvta.to.shared.u64 t, %1; cvt.u32.u64 %0, t; }"
        : "=r"(a) : "l"(p));
    return a;
}

__device__ __forceinline__ void cpa16(unsigned dst, const __nv_bfloat16* src) {
    size_t g;
    asm("cvta.to.global.u64 %0, %1;" : "=l"(g) : "l"(src));
    asm volatile("cp.async.cg.shared.global [%0], [%1], 16;" :: "r"(dst), "l"(g));
}

__device__ __forceinline__ void ldsm4(unsigned* r, unsigned a) {
    asm volatile("ldmatrix.sync.aligned.m8n8.x4.shared.b16 {%0,%1,%2,%3}, [%4];"
        : "=r"(r[0]), "=r"(r[1]), "=r"(r[2]), "=r"(r[3]) : "r"(a));
}

__device__ __forceinline__ void ldsm4t(unsigned* r, unsigned a) {
    asm volatile("ldmatrix.sync.aligned.m8n8.x4.trans.shared.b16 {%0,%1,%2,%3}, [%4];"
        : "=r"(r[0]), "=r"(r[1]), "=r"(r[2]), "=r"(r[3]) : "r"(a));
}

__device__ __forceinline__ void mma16816(float* d, const unsigned* a, const unsigned* b) {
    asm volatile(
        "mma.sync.aligned.m16n8k16.row.col.f32.bf16.bf16.f32 "
        "{%0,%1,%2,%3}, {%4,%5,%6,%7}, {%8,%9}, {%0,%1,%2,%3};"
        : "+f"(d[0]), "+f"(d[1]), "+f"(d[2]), "+f"(d[3])
        : "r"(a[0]), "r"(a[1]), "r"(a[2]), "r"(a[3]), "r"(b[0]), "r"(b[1]));
}

// split a float pair into packed bf16x2 hi + lo
__device__ __forceinline__ void split2(float a, float b, unsigned& hi, unsigned& lo) {
    __nv_bfloat16 ha = __float2bfloat16(a), hb = __float2bfloat16(b);
    __nv_bfloat16 la = __float2bfloat16(a - __bfloat162float(ha));
    __nv_bfloat16 lb = __float2bfloat16(b - __bfloat162float(hb));
    __nv_bfloat162 H = __halves2bfloat162(ha, hb);
    __nv_bfloat162 L = __halves2bfloat162(la, lb);
    hi = *(unsigned*)&H; lo = *(unsigned*)&L;
}

// ---------------- prep: fp32 -> bf16 hi + lo split ---------------------------
__global__ __launch_bounds__(256) void split_kernel(const float* __restrict__ src,
                                                    int mode, int n4) {
    int i = blockIdx.x * 256 + threadIdx.x;
    if (i >= n4) return;
    __nv_bfloat16* h = (mode == 0) ? gx_h : (mode == 1) ? gwq_h : gwp_h;
    __nv_bfloat16* l = (mode == 0) ? gx_l : (mode == 1) ? gwq_l : gwp_l;
    float4 v = ((const float4*)src)[i];
    unsigned h01, l01, h23, l23;
    split2(v.x, v.y, h01, l01);
    split2(v.z, v.w, h23, l23);
    unsigned* hp = (unsigned*)h + 2 * (size_t)i;
    unsigned* lp = (unsigned*)l + 2 * (size_t)i;
    hp[0] = h01; hp[1] = h23;
    lp[0] = l01; lp[1] = l23;
}

// =============================================================================
// mma.sync GEMM: out[m,d] = sum_c A[m,c]*B[d,c], bf16 split 3-pass, fp32 acc.
// CTA 128x128, BK=32, 8 warps x (64x32). smem rows padded to 80B.
// __launch_bounds__(256,2): cap regs at 128 so 2 CTAs/SM fit (R10 regression:
// epilogue pushed regs to 138 -> 1 CTA/SM -> tensor 62%->51%).
// Single-sync double buffer: wait -> sync -> prefetch(next) -> compute(cur).
// EPI 0: A=x, B=Wqkv, scatter epilogue -> g_{q,k,v}{h,l} bf16 (q pre-scaled)
// EPI 1: A=attn out (go), B=Wproj, epilogue adds bias -> out fp32
// =============================================================================
#define LDBY 80
#define TILE_B (128*LDBY)
#define BUF_B  (4*TILE_B)
#define GEMM_SMEM (2*BUF_B)
#define NCHUNK (CC/32)

template<int EPI>
__global__ __launch_bounds__(256, 2) void mma_gemm(const float* __restrict__ bias,
                                                   float* __restrict__ out) {
    extern __shared__ char sm[];
    const unsigned sb = smem_u32(sm);
    const int tid  = threadIdx.x;
    const int lane = tid & 31, wid = tid >> 5;
    const int wm = wid & 1, wn = wid >> 1;
    const int rowBase = blockIdx.y * 128;
    const int colBase = blockIdx.x * 128;

    const __nv_bfloat16* Ah = EPI ? go_h  : gx_h;
    const __nv_bfloat16* Al = EPI ? go_l  : gx_l;
    const __nv_bfloat16* Bh = EPI ? gwp_h : gwq_h;
    const __nv_bfloat16* Bl = EPI ? gwp_l : gwq_l;

    auto prefetch = [&](int buf, int k0) {
        unsigned base = sb + buf * BUF_B;
#pragma unroll
        for (int t = 0; t < 2; t++) {
            int s = tid + t * 256;
            int r = s >> 2, c = s & 3;
            unsigned d = base + r * LDBY + c * 16;
            size_t ao = (size_t)(rowBase + r) * CC + k0 + c * 8;
            size_t bo = (size_t)(colBase + r) * CC + k0 + c * 8;
            cpa16(d + 0*TILE_B, Ah + ao);
            cpa16(d + 1*TILE_B, Al + ao);
            cpa16(d + 2*TILE_B, Bh + bo);
            cpa16(d + 3*TILE_B, Bl + bo);
        }
        asm volatile("cp.async.commit_group;" ::: "memory");
    };

    float acc[4][4][4];
#pragma unroll
    for (int a = 0; a < 4; a++)
#pragma unroll
        for (int b = 0; b < 4; b++)
#pragma unroll
            for (int e = 0; e < 4; e++) acc[a][b][e] = 0.f;

    prefetch(0, 0);
    for (int ch = 0; ch < NCHUNK; ch++) {
        int buf = ch & 1;
        // wait for this chunk's data; the sync also guarantees the previous
        // compute on buf^1 is finished, so prefetching into it is safe.
        asm volatile("cp.async.wait_group 0;" ::: "memory");
        __syncthreads();
        if (ch + 1 < NCHUNK) prefetch(buf ^ 1, (ch + 1) * 32);

        unsigned base = sb + buf * BUF_B;
#pragma unroll
        for (int ks = 0; ks < 2; ks++) {
            unsigned ah[4][4], al[4][4], bh[4][2], bl[4][2], tmp[4];
            unsigned aaddr = base + (wm*64 + (lane & 15)) * LDBY
                           + ks*32 + (lane >> 4) * 16;
#pragma unroll
            for (int mt = 0; mt < 4; mt++) {
                ldsm4(ah[mt], aaddr + mt * 16 * LDBY);
                ldsm4(al[mt], aaddr + mt * 16 * LDBY + TILE_B);
            }
            unsigned baddr = base + 2*TILE_B
                           + (wn*32 + (lane & 7) + ((lane >> 4) & 1) * 8) * LDBY
                           + ks*32 + ((lane >> 3) & 1) * 16;
#pragma unroll
            for (int np = 0; np < 2; np++) {
                ldsm4(tmp, baddr + np * 16 * LDBY);
                bh[2*np][0]=tmp[0]; bh[2*np][1]=tmp[1];
                bh[2*np+1][0]=tmp[2]; bh[2*np+1][1]=tmp[3];
                ldsm4(tmp, baddr + np * 16 * LDBY + TILE_B);
                bl[2*np][0]=tmp[0]; bl[2*np][1]=tmp[1];
                bl[2*np+1][0]=tmp[2]; bl[2*np+1][1]=tmp[3];
            }
#pragma unroll
            for (int mt = 0; mt < 4; mt++)
#pragma unroll
                for (int nt = 0; nt < 4; nt++) {
                    mma16816(acc[mt][nt], ah[mt], bh[nt]);
                    mma16816(acc[mt][nt], ah[mt], bl[nt]);
                    mma16816(acc[mt][nt], al[mt], bh[nt]);
                }
        }
    }
    __syncthreads();

#pragma unroll
    for (int mt = 0; mt < 4; mt++) {
        int mbase = rowBase + wm*64 + mt*16 + (lane >> 2);
#pragma unroll
        for (int half = 0; half < 2; half++) {
            int mm = mbase + half * 8;
#pragma unroll
            for (int nt = 0; nt < 4; nt++) {
                float e0 = acc[mt][nt][half*2 + 0];
                float e1 = acc[mt][nt][half*2 + 1];
                int d0 = colBase + wn*32 + nt*8 + 2*(lane & 3);
                if (EPI == 0) {
                    int g = d0 >> 10, rem = d0 & 1023;
                    int h = rem >> 6, hd = rem & 63;
                    float sc = (g == 0) ? QK_SCALE : 1.0f;
                    __nv_bfloat16* dh = (g == 0) ? g_qh : (g == 1) ? g_kh : g_vh;
                    __nv_bfloat16* dl = (g == 0) ? g_ql : (g == 1) ? g_kl : g_vl;
                    int b = mm >> 9, n = mm & 511;
                    size_t idx = ((size_t)((b*HH + h)*NN + n)) * HD + hd;
                    unsigned hi, lo;
                    split2(e0 * sc, e1 * sc, hi, lo);
                    *(unsigned*)&dh[idx] = hi;
                    *(unsigned*)&dl[idx] = lo;
                } else {
                    float2 bv = *(const float2*)&bias[d0];
                    *(float2*)&out[(size_t)mm * CC + d0] = make_float2(e0 + bv.x, e1 + bv.y);
                }
            }
        }
    }
}

// =============================================================================
// FlashAttention-2 style mma attention (unchanged from R10 — protect the win).
// =============================================================================
#define PIT 144
#define AQH 0
#define AQL (128*PIT)
#define ABUF (2*128*PIT)
#define ABUFSZ (4*64*PIT)
#define AKH 0
#define AKL (64*PIT)
#define AVH (2*64*PIT)
#define AVL (3*64*PIT)
#define AMS (ABUF + 2*ABUFSZ)
#define ATT_SMEM (AMS + NN*4)

__global__ __launch_bounds__(256) void attn_mma(const float* __restrict__ mask) {
    extern __shared__ char smA[];
    const unsigned sb = smem_u32(smA);
    const int tid = threadIdx.x;
    const int lane = tid & 31, wid = tid >> 5;
    const int qt = blockIdx.x, h = blockIdx.y, b = blockIdx.z;
    const size_t headoff = (size_t)((b*HH + h)*NN) * HD;
    const __nv_bfloat16* Qh = g_qh + headoff + (size_t)qt*128*HD;
    const __nv_bfloat16* Ql = g_ql + headoff + (size_t)qt*128*HD;
    const __nv_bfloat16* Kh = g_kh + headoff;
    const __nv_bfloat16* Kl = g_kl + headoff;
    const __nv_bfloat16* Vh = g_vh + headoff;
    const __nv_bfloat16* Vl = g_vl + headoff;
    float* Ms = (float*)(smA + AMS);

#pragma unroll
    for (int i = 0; i < 8; i++) {
        int idx = tid + i*256;
        int arr = idx >> 10, rem = idx & 1023;
        int r = rem >> 3, c = rem & 7;
        const __nv_bfloat16* src = (arr ? Ql : Qh) + (size_t)r*HD + c*8;
        cpa16(sb + (arr ? AQL : AQH) + r*PIT + c*16, src);
    }
    asm volatile("cp.async.commit_group;" ::: "memory");

    for (int i = tid; i < NN; i += 256) Ms[i] = mask[b*NN + i];

    auto load_kv = [&](int buf, int t) {
        unsigned dstb = sb + ABUF + buf*ABUFSZ;
#pragma unroll
        for (int i = 0; i < 8; i++) {
            int idx = tid + i*256;
            int arr = idx >> 9, rem = idx & 511;
            int r = rem >> 3, c = rem & 7;
            const __nv_bfloat16* src =
                (arr == 0 ? Kh : arr == 1 ? Kl : arr == 2 ? Vh : Vl)
                + (size_t)(t*64 + r)*HD + c*8;
            cpa16(dstb + arr*(64*PIT) + r*PIT + c*16, src);
        }
        asm volatile("cp.async.commit_group;" ::: "memory");
    };

    load_kv(0, 0);
    asm volatile("cp.async.wait_group 1;" ::: "memory");   // Q ready
    __syncthreads();

    unsigned qfh[4][4], qfl[4][4];
#pragma unroll
    for (int kc = 0; kc < 4; kc++) {
        unsigned a = sb + (wid*16 + (lane & 15))*PIT + kc*32 + (lane >> 4)*16;
        ldsm4(qfh[kc], a + AQH);
        ldsm4(qfl[kc], a + AQL);
    }

    float of[8][4];
#pragma unroll
    for (int j = 0; j < 8; j++)
#pragma unroll
        for (int e = 0; e < 4; e++) of[j][e] = 0.f;
    float m0 = -1e30f, m1 = -1e30f, l0 = 0.f, l1 = 0.f;
    const unsigned FULL = 0xffffffffu;

    for (int t = 0; t < 8; t++) {
        int buf = t & 1;
        if (t < 7) {
            load_kv(buf ^ 1, t + 1);
            asm volatile("cp.async.wait_group 1;" ::: "memory");
        } else {
            asm volatile("cp.async.wait_group 0;" ::: "memory");
        }
        __syncthreads();
        unsigned kb = sb + ABUF + buf*ABUFSZ;

        float sf[8][4];
#pragma unroll
        for (int j = 0; j < 8; j++)
#pragma unroll
            for (int e = 0; e < 4; e++) sf[j][e] = 0.f;

#pragma unroll
        for (int kc = 0; kc < 4; kc++) {
            unsigned kf[8][2], tmp[4];
            unsigned ab = kb + ((lane & 7) + ((lane >> 4) & 1)*8)*PIT
                        + kc*32 + ((lane >> 3) & 1)*16;
#pragma unroll
            for (int np = 0; np < 4; np++) {
                ldsm4(tmp, ab + AKH + np*16*PIT);
                kf[2*np][0]=tmp[0]; kf[2*np][1]=tmp[1];
                kf[2*np+1][0]=tmp[2]; kf[2*np+1][1]=tmp[3];
            }
#pragma unroll
            for (int nf = 0; nf < 8; nf++) {
                mma16816(sf[nf], qfh[kc], kf[nf]);
                mma16816(sf[nf], qfl[kc], kf[nf]);
            }
#pragma unroll
            for (int np = 0; np < 4; np++) {
                ldsm4(tmp, ab + AKL + np*16*PIT);
                kf[2*np][0]=tmp[0]; kf[2*np][1]=tmp[1];
                kf[2*np+1][0]=tmp[2]; kf[2*np+1][1]=tmp[3];
            }
#pragma unroll
            for (int nf = 0; nf < 8; nf++)
                mma16816(sf[nf], qfh[kc], kf[nf]);
        }

        float mx0 = -1e30f, mx1 = -1e30f;
#pragma unroll
        for (int j = 0; j < 8; j++) {
            int col = t*64 + j*8 + 2*(lane & 3);
            float2 mb = *(const float2*)&Ms[col];
            sf[j][0] += mb.x; sf[j][1] += mb.y;
            sf[j][2] += mb.x; sf[j][3] += mb.y;
            mx0 = fmaxf(mx0, fmaxf(sf[j][0], sf[j][1]));
            mx1 = fmaxf(mx1, fmaxf(sf[j][2], sf[j][3]));
        }
        mx0 = fmaxf(mx0, __shfl_xor_sync(FULL, mx0, 1));
        mx0 = fmaxf(mx0, __shfl_xor_sync(FULL, mx0, 2));
        mx1 = fmaxf(mx1, __shfl_xor_sync(FULL, mx1, 1));
        mx1 = fmaxf(mx1, __shfl_xor_sync(FULL, mx1, 2));
        float nm0 = fmaxf(m0, mx0), nm1 = fmaxf(m1, mx1);
        float c0 = __expf(m0 - nm0), c1 = __expf(m1 - nm1);
        float s0 = 0.f, s1 = 0.f;
#pragma unroll
        for (int j = 0; j < 8; j++) {
            sf[j][0] = __expf(sf[j][0] - nm0);
            sf[j][1] = __expf(sf[j][1] - nm0);
            sf[j][2] = __expf(sf[j][2] - nm1);
            sf[j][3] = __expf(sf[j][3] - nm1);
            s0 += sf[j][0] + sf[j][1];
            s1 += sf[j][2] + sf[j][3];
        }
        s0 += __shfl_xor_sync(FULL, s0, 1);
        s0 += __shfl_xor_sync(FULL, s0, 2);
        s1 += __shfl_xor_sync(FULL, s1, 1);
        s1 += __shfl_xor_sync(FULL, s1, 2);
        l0 = l0 * c0 + s0; l1 = l1 * c1 + s1;
        m0 = nm0; m1 = nm1;
#pragma unroll
        for (int j = 0; j < 8; j++) {
            of[j][0] *= c0; of[j][1] *= c0;
            of[j][2] *= c1; of[j][3] *= c1;
        }

#pragma unroll
        for (int c = 0; c < 4; c++) {
            unsigned pah[4], pal[4];
            split2(sf[2*c][0],   sf[2*c][1],   pah[0], pal[0]);
            split2(sf[2*c][2],   sf[2*c][3],   pah[1], pal[1]);
            split2(sf[2*c+1][0], sf[2*c+1][1], pah[2], pal[2]);
            split2(sf[2*c+1][2], sf[2*c+1][3], pah[3], pal[3]);

            unsigned vf[8][2], tmp[4];
            unsigned vb = kb + (16*c + (lane & 7) + ((lane >> 3) & 1)*8)*PIT
                        + ((lane >> 4) & 1)*16;
#pragma unroll
            for (int g = 0; g < 4; g++) {
                ldsm4t(tmp, vb + AVH + g*32);
                vf[2*g][0]=tmp[0]; vf[2*g][1]=tmp[1];
                vf[2*g+1][0]=tmp[2]; vf[2*g+1][1]=tmp[3];
            }
#pragma unroll
            for (int nf = 0; nf < 8; nf++) {
                mma16816(of[nf], pah, vf[nf]);
                mma16816(of[nf], pal, vf[nf]);
            }
#pragma unroll
            for (int g = 0; g < 4; g++) {
                ldsm4t(tmp, vb + AVL + g*32);
                vf[2*g][0]=tmp[0]; vf[2*g][1]=tmp[1];
                vf[2*g+1][0]=tmp[2]; vf[2*g+1][1]=tmp[3];
            }
#pragma unroll
            for (int nf = 0; nf < 8; nf++)
                mma16816(of[nf], pah, vf[nf]);
        }
        __syncthreads();
    }

    float inv0 = 1.0f / l0, inv1 = 1.0f / l1;
    int q0 = qt*128 + wid*16 + (lane >> 2);
#pragma unroll
    for (int j = 0; j < 8; j++) {
        int d = h*HD + j*8 + 2*(lane & 3);
        unsigned hi, lo;
        size_t i0 = (size_t)(b*NN + q0) * CC + d;
        split2(of[j][0]*inv0, of[j][1]*inv0, hi, lo);
        *(unsigned*)&go_h[i0] = hi; *(unsigned*)&go_l[i0] = lo;
        size_t i1 = (size_t)(b*NN + q0 + 8) * CC + d;
        split2(of[j][2]*inv1, of[j][3]*inv1, hi, lo);
        *(unsigned*)&go_h[i1] = hi; *(unsigned*)&go_l[i1] = lo;
    }
}

// =============================================================================
extern "C" void kernel_launch(void* const* d_in, const int* in_sizes, int n_in,
                              void* d_out, int out_size) {
    const float* x     = (const float*)d_in[0];
    const float* mask  = (const float*)d_in[1];
    const float* Wqkv  = (const float*)d_in[2];
    const float* Wproj = (const float*)d_in[3];
    const float* bproj = (const float*)d_in[4];
    float* out = (float*)d_out;

    cudaFuncSetAttribute(mma_gemm<0>, cudaFuncAttributeMaxDynamicSharedMemorySize, GEMM_SMEM);
    cudaFuncSetAttribute(mma_gemm<1>, cudaFuncAttributeMaxDynamicSharedMemorySize, GEMM_SMEM);
    cudaFuncSetAttribute(attn_mma,    cudaFuncAttributeMaxDynamicSharedMemorySize, ATT_SMEM);

    int n4x = BB*NN*CC/4, n4q = 3*CC*CC/4, n4p = CC*CC/4;
    split_kernel<<<(n4x + 255)/256, 256>>>(x, 0, n4x);
    split_kernel<<<(n4q + 255)/256, 256>>>(Wqkv, 1, n4q);
    split_kernel<<<(n4p + 255)/256, 256>>>(Wproj, 2, n4p);

    dim3 g1(3*CC/128, BB*NN/128);     // (24, 128)
    mma_gemm<0><<<g1, 256, GEMM_SMEM>>>(nullptr, nullptr);

    dim3 g2(NN/128, HH, BB);          // (4, 16, 32)
    attn_mma<<<g2, 256, ATT_SMEM>>>(mask);

    dim3 g3(CC/128, BB*NN/128);       // (8, 128)
    mma_gemm<1><<<g3, 256, GEMM_SMEM>>>(bproj, out);
}

// round 12
// speedup vs baseline: 1.6438x; 1.6438x over previous
#include <cuda_runtime.h>
#include <cuda_bf16.h>

#define BB 32
#define NN 512
#define CC 1024
#define HH 16
#define HD 64
#define QK_SCALE 0.125f   // 64^-0.5

// ---------------- device-global scratch (alloc-free path) --------------------
// q/k/v as bf16 hi/lo, [B,H,N,HD]; q pre-scaled by QK_SCALE
__device__ __align__(16) __nv_bfloat16 g_qh[(size_t)BB*HH*NN*HD];
__device__ __align__(16) __nv_bfloat16 g_ql[(size_t)BB*HH*NN*HD];
__device__ __align__(16) __nv_bfloat16 g_kh[(size_t)BB*HH*NN*HD];
__device__ __align__(16) __nv_bfloat16 g_kl[(size_t)BB*HH*NN*HD];
__device__ __align__(16) __nv_bfloat16 g_vh[(size_t)BB*HH*NN*HD];
__device__ __align__(16) __nv_bfloat16 g_vl[(size_t)BB*HH*NN*HD];
// input / weight splits
__device__ __align__(16) __nv_bfloat16 gx_h[(size_t)BB*NN*CC];
__device__ __align__(16) __nv_bfloat16 gx_l[(size_t)BB*NN*CC];
__device__ __align__(16) __nv_bfloat16 gwq_h[(size_t)3*CC*CC];
__device__ __align__(16) __nv_bfloat16 gwq_l[(size_t)3*CC*CC];
__device__ __align__(16) __nv_bfloat16 gwp_h[(size_t)CC*CC];
__device__ __align__(16) __nv_bfloat16 gwp_l[(size_t)CC*CC];
// attention output hi/lo [B,N,C]
__device__ __align__(16) __nv_bfloat16 go_h[(size_t)BB*NN*CC];
__device__ __align__(16) __nv_bfloat16 go_l[(size_t)BB*NN*CC];

// ---------------- baseline-ISA helpers (sm_80+) ------------------------------
__device__ __forceinline__ unsigned smem_u32(const void* p) {
    unsigned a;
    asm("{ .reg .u64 t; cvta.to.shared.u64 t, %1; cvt.u32.u64 %0, t; }"
        : "=r"(a) : "l"(p));
    return a;
}

__device__ __forceinline__ void cpa16(unsigned dst, const __nv_bfloat16* src) {
    size_t g;
    asm("cvta.to.global.u64 %0, %1;" : "=l"(g) : "l"(src));
    asm volatile("cp.async.cg.shared.global [%0], [%1], 16;" :: "r"(dst), "l"(g));
}

__device__ __forceinline__ void ldsm4(unsigned* r, unsigned a) {
    asm volatile("ldmatrix.sync.aligned.m8n8.x4.shared.b16 {%0,%1,%2,%3}, [%4];"
        : "=r"(r[0]), "=r"(r[1]), "=r"(r[2]), "=r"(r[3]) : "r"(a));
}

__device__ __forceinline__ void ldsm4t(unsigned* r, unsigned a) {
    asm volatile("ldmatrix.sync.aligned.m8n8.x4.trans.shared.b16 {%0,%1,%2,%3}, [%4];"
        : "=r"(r[0]), "=r"(r[1]), "=r"(r[2]), "=r"(r[3]) : "r"(a));
}

__device__ __forceinline__ void mma16816(float* d, const unsigned* a, const unsigned* b) {
    asm volatile(
        "mma.sync.aligned.m16n8k16.row.col.f32.bf16.bf16.f32 "
        "{%0,%1,%2,%3}, {%4,%5,%6,%7}, {%8,%9}, {%0,%1,%2,%3};"
        : "+f"(d[0]), "+f"(d[1]), "+f"(d[2]), "+f"(d[3])
        : "r"(a[0]), "r"(a[1]), "r"(a[2]), "r"(a[3]), "r"(b[0]), "r"(b[1]));
}

// split a float pair into packed bf16x2 hi + lo
__device__ __forceinline__ void split2(float a, float b, unsigned& hi, unsigned& lo) {
    __nv_bfloat16 ha = __float2bfloat16(a), hb = __float2bfloat16(b);
    __nv_bfloat16 la = __float2bfloat16(a - __bfloat162float(ha));
    __nv_bfloat16 lb = __float2bfloat16(b - __bfloat162float(hb));
    __nv_bfloat162 H = __halves2bfloat162(ha, hb);
    __nv_bfloat162 L = __halves2bfloat162(la, lb);
    hi = *(unsigned*)&H; lo = *(unsigned*)&L;
}

// ---------------- prep: fp32 -> bf16 hi + lo split ---------------------------
__global__ __launch_bounds__(256) void split_kernel(const float* __restrict__ src,
                                                    int mode, int n4) {
    int i = blockIdx.x * 256 + threadIdx.x;
    if (i >= n4) return;
    __nv_bfloat16* h = (mode == 0) ? gx_h : (mode == 1) ? gwq_h : gwp_h;
    __nv_bfloat16* l = (mode == 0) ? gx_l : (mode == 1) ? gwq_l : gwp_l;
    float4 v = ((const float4*)src)[i];
    unsigned h01, l01, h23, l23;
    split2(v.x, v.y, h01, l01);
    split2(v.z, v.w, h23, l23);
    unsigned* hp = (unsigned*)h + 2 * (size_t)i;
    unsigned* lp = (unsigned*)l + 2 * (size_t)i;
    hp[0] = h01; hp[1] = h23;
    lp[0] = l01; lp[1] = l23;
}

// =============================================================================
// mma.sync GEMM: out[m,d] = sum_c A[m,c]*B[d,c], bf16 split 3-pass, fp32 acc.
// CTA 128x128, BK=32, 8 warps x (64x32). smem rows padded to 80B.
// R12: R9's proven two-sync pipeline + B-fragment register reuse (load bh,
// run hh+lh passes, overwrite with bl, run hl pass) so peak live regs fit the
// 128-reg budget implied by __launch_bounds__(256,2) WITHOUT mainloop spills
// (R11 regression: cap without demand reduction -> spills -> L1 40%, 1406us).
// EPI 0: A=x, B=Wqkv, scatter epilogue -> g_{q,k,v}{h,l} bf16 (q pre-scaled)
// EPI 1: A=attn out (go), B=Wproj, epilogue adds bias -> out fp32
// =============================================================================
#define LDBY 80
#define TILE_B (128*LDBY)
#define BUF_B  (4*TILE_B)
#define GEMM_SMEM (2*BUF_B)
#define NCHUNK (CC/32)

template<int EPI>
__global__ __launch_bounds__(256, 2) void mma_gemm(const float* __restrict__ bias,
                                                   float* __restrict__ out) {
    extern __shared__ char sm[];
    const unsigned sb = smem_u32(sm);
    const int tid  = threadIdx.x;
    const int lane = tid & 31, wid = tid >> 5;
    const int wm = wid & 1, wn = wid >> 1;
    const int rowBase = blockIdx.y * 128;
    const int colBase = blockIdx.x * 128;

    const __nv_bfloat16* Ah = EPI ? go_h  : gx_h;
    const __nv_bfloat16* Al = EPI ? go_l  : gx_l;
    const __nv_bfloat16* Bh = EPI ? gwp_h : gwq_h;
    const __nv_bfloat16* Bl = EPI ? gwp_l : gwq_l;

    auto prefetch = [&](int buf, int k0) {
        unsigned base = sb + buf * BUF_B;
#pragma unroll
        for (int t = 0; t < 2; t++) {
            int s = tid + t * 256;
            int r = s >> 2, c = s & 3;
            unsigned d = base + r * LDBY + c * 16;
            size_t ao = (size_t)(rowBase + r) * CC + k0 + c * 8;
            size_t bo = (size_t)(colBase + r) * CC + k0 + c * 8;
            cpa16(d + 0*TILE_B, Ah + ao);
            cpa16(d + 1*TILE_B, Al + ao);
            cpa16(d + 2*TILE_B, Bh + bo);
            cpa16(d + 3*TILE_B, Bl + bo);
        }
        asm volatile("cp.async.commit_group;" ::: "memory");
    };

    float acc[4][4][4];
#pragma unroll
    for (int a = 0; a < 4; a++)
#pragma unroll
        for (int b = 0; b < 4; b++)
#pragma unroll
            for (int e = 0; e < 4; e++) acc[a][b][e] = 0.f;

    prefetch(0, 0);
    for (int ch = 0; ch < NCHUNK; ch++) {
        int buf = ch & 1;
        if (ch + 1 < NCHUNK) {
            prefetch(buf ^ 1, (ch + 1) * 32);
            asm volatile("cp.async.wait_group 1;" ::: "memory");
        } else {
            asm volatile("cp.async.wait_group 0;" ::: "memory");
        }
        __syncthreads();
        unsigned base = sb + buf * BUF_B;
#pragma unroll
        for (int ks = 0; ks < 2; ks++) {
            unsigned ah[4][4], al[4][4], bf[4][2], tmp[4];
            unsigned aaddr = base + (wm*64 + (lane & 15)) * LDBY
                           + ks*32 + (lane >> 4) * 16;
#pragma unroll
            for (int mt = 0; mt < 4; mt++) {
                ldsm4(ah[mt], aaddr + mt * 16 * LDBY);
                ldsm4(al[mt], aaddr + mt * 16 * LDBY + TILE_B);
            }
            unsigned baddr = base + 2*TILE_B
                           + (wn*32 + (lane & 7) + ((lane >> 4) & 1) * 8) * LDBY
                           + ks*32 + ((lane >> 3) & 1) * 16;
            // --- bh resident: hh + lh passes ---
#pragma unroll
            for (int np = 0; np < 2; np++) {
                ldsm4(tmp, baddr + np * 16 * LDBY);
                bf[2*np][0]=tmp[0]; bf[2*np][1]=tmp[1];
                bf[2*np+1][0]=tmp[2]; bf[2*np+1][1]=tmp[3];
            }
#pragma unroll
            for (int mt = 0; mt < 4; mt++)
#pragma unroll
                for (int nt = 0; nt < 4; nt++) {
                    mma16816(acc[mt][nt], ah[mt], bf[nt]);   // hi*hi
                    mma16816(acc[mt][nt], al[mt], bf[nt]);   // lo*hi
                }
            // --- overwrite with bl: hl pass ---
#pragma unroll
            for (int np = 0; np < 2; np++) {
                ldsm4(tmp, baddr + np * 16 * LDBY + TILE_B);
                bf[2*np][0]=tmp[0]; bf[2*np][1]=tmp[1];
                bf[2*np+1][0]=tmp[2]; bf[2*np+1][1]=tmp[3];
            }
#pragma unroll
            for (int mt = 0; mt < 4; mt++)
#pragma unroll
                for (int nt = 0; nt < 4; nt++)
                    mma16816(acc[mt][nt], ah[mt], bf[nt]);   // hi*lo
        }
        __syncthreads();
    }

#pragma unroll
    for (int mt = 0; mt < 4; mt++) {
        int mbase = rowBase + wm*64 + mt*16 + (lane >> 2);
#pragma unroll
        for (int half = 0; half < 2; half++) {
            int mm = mbase + half * 8;
#pragma unroll
            for (int nt = 0; nt < 4; nt++) {
                float e0 = acc[mt][nt][half*2 + 0];
                float e1 = acc[mt][nt][half*2 + 1];
                int d0 = colBase + wn*32 + nt*8 + 2*(lane & 3);
                if (EPI == 0) {
                    int g = d0 >> 10, rem = d0 & 1023;
                    int h = rem >> 6, hd = rem & 63;
                    float sc = (g == 0) ? QK_SCALE : 1.0f;
                    __nv_bfloat16* dh = (g == 0) ? g_qh : (g == 1) ? g_kh : g_vh;
                    __nv_bfloat16* dl = (g == 0) ? g_ql : (g == 1) ? g_kl : g_vl;
                    int b = mm >> 9, n = mm & 511;
                    size_t idx = ((size_t)((b*HH + h)*NN + n)) * HD + hd;
                    unsigned hi, lo;
                    split2(e0 * sc, e1 * sc, hi, lo);
                    *(unsigned*)&dh[idx] = hi;
                    *(unsigned*)&dl[idx] = lo;
                } else {
                    float2 bv = *(const float2*)&bias[d0];
                    *(float2*)&out[(size_t)mm * CC + d0] = make_float2(e0 + bv.x, e1 + bv.y);
                }
            }
        }
    }
}

// =============================================================================
// FlashAttention-2 style mma attention (unchanged from R10 — protect the win).
// =============================================================================
#define PIT 144
#define AQH 0
#define AQL (128*PIT)
#define ABUF (2*128*PIT)
#define ABUFSZ (4*64*PIT)
#define AKH 0
#define AKL (64*PIT)
#define AVH (2*64*PIT)
#define AVL (3*64*PIT)
#define AMS (ABUF + 2*ABUFSZ)
#define ATT_SMEM (AMS + NN*4)

__global__ __launch_bounds__(256) void attn_mma(const float* __restrict__ mask) {
    extern __shared__ char smA[];
    const unsigned sb = smem_u32(smA);
    const int tid = threadIdx.x;
    const int lane = tid & 31, wid = tid >> 5;
    const int qt = blockIdx.x, h = blockIdx.y, b = blockIdx.z;
    const size_t headoff = (size_t)((b*HH + h)*NN) * HD;
    const __nv_bfloat16* Qh = g_qh + headoff + (size_t)qt*128*HD;
    const __nv_bfloat16* Ql = g_ql + headoff + (size_t)qt*128*HD;
    const __nv_bfloat16* Kh = g_kh + headoff;
    const __nv_bfloat16* Kl = g_kl + headoff;
    const __nv_bfloat16* Vh = g_vh + headoff;
    const __nv_bfloat16* Vl = g_vl + headoff;
    float* Ms = (float*)(smA + AMS);

#pragma unroll
    for (int i = 0; i < 8; i++) {
        int idx = tid + i*256;
        int arr = idx >> 10, rem = idx & 1023;
        int r = rem >> 3, c = rem & 7;
        const __nv_bfloat16* src = (arr ? Ql : Qh) + (size_t)r*HD + c*8;
        cpa16(sb + (arr ? AQL : AQH) + r*PIT + c*16, src);
    }
    asm volatile("cp.async.commit_group;" ::: "memory");

    for (int i = tid; i < NN; i += 256) Ms[i] = mask[b*NN + i];

    auto load_kv = [&](int buf, int t) {
        unsigned dstb = sb + ABUF + buf*ABUFSZ;
#pragma unroll
        for (int i = 0; i < 8; i++) {
            int idx = tid + i*256;
            int arr = idx >> 9, rem = idx & 511;
            int r = rem >> 3, c = rem & 7;
            const __nv_bfloat16* src =
                (arr == 0 ? Kh : arr == 1 ? Kl : arr == 2 ? Vh : Vl)
                + (size_t)(t*64 + r)*HD + c*8;
            cpa16(dstb + arr*(64*PIT) + r*PIT + c*16, src);
        }
        asm volatile("cp.async.commit_group;" ::: "memory");
    };

    load_kv(0, 0);
    asm volatile("cp.async.wait_group 1;" ::: "memory");   // Q ready
    __syncthreads();

    unsigned qfh[4][4], qfl[4][4];
#pragma unroll
    for (int kc = 0; kc < 4; kc++) {
        unsigned a = sb + (wid*16 + (lane & 15))*PIT + kc*32 + (lane >> 4)*16;
        ldsm4(qfh[kc], a + AQH);
        ldsm4(qfl[kc], a + AQL);
    }

    float of[8][4];
#pragma unroll
    for (int j = 0; j < 8; j++)
#pragma unroll
        for (int e = 0; e < 4; e++) of[j][e] = 0.f;
    float m0 = -1e30f, m1 = -1e30f, l0 = 0.f, l1 = 0.f;
    const unsigned FULL = 0xffffffffu;

    for (int t = 0; t < 8; t++) {
        int buf = t & 1;
        if (t < 7) {
            load_kv(buf ^ 1, t + 1);
            asm volatile("cp.async.wait_group 1;" ::: "memory");
        } else {
            asm volatile("cp.async.wait_group 0;" ::: "memory");
        }
        __syncthreads();
        unsigned kb = sb + ABUF + buf*ABUFSZ;

        float sf[8][4];
#pragma unroll
        for (int j = 0; j < 8; j++)
#pragma unroll
            for (int e = 0; e < 4; e++) sf[j][e] = 0.f;

#pragma unroll
        for (int kc = 0; kc < 4; kc++) {
            unsigned kf[8][2], tmp[4];
            unsigned ab = kb + ((lane & 7) + ((lane >> 4) & 1)*8)*PIT
                        + kc*32 + ((lane >> 3) & 1)*16;
#pragma unroll
            for (int np = 0; np < 4; np++) {
                ldsm4(tmp, ab + AKH + np*16*PIT);
                kf[2*np][0]=tmp[0]; kf[2*np][1]=tmp[1];
                kf[2*np+1][0]=tmp[2]; kf[2*np+1][1]=tmp[3];
            }
#pragma unroll
            for (int nf = 0; nf < 8; nf++) {
                mma16816(sf[nf], qfh[kc], kf[nf]);
                mma16816(sf[nf], qfl[kc], kf[nf]);
            }
#pragma unroll
            for (int np = 0; np < 4; np++) {
                ldsm4(tmp, ab + AKL + np*16*PIT);
                kf[2*np][0]=tmp[0]; kf[2*np][1]=tmp[1];
                kf[2*np+1][0]=tmp[2]; kf[2*np+1][1]=tmp[3];
            }
#pragma unroll
            for (int nf = 0; nf < 8; nf++)
                mma16816(sf[nf], qfh[kc], kf[nf]);
        }

        float mx0 = -1e30f, mx1 = -1e30f;
#pragma unroll
        for (int j = 0; j < 8; j++) {
            int col = t*64 + j*8 + 2*(lane & 3);
            float2 mb = *(const float2*)&Ms[col];
            sf[j][0] += mb.x; sf[j][1] += mb.y;
            sf[j][2] += mb.x; sf[j][3] += mb.y;
            mx0 = fmaxf(mx0, fmaxf(sf[j][0], sf[j][1]));
            mx1 = fmaxf(mx1, fmaxf(sf[j][2], sf[j][3]));
        }
        mx0 = fmaxf(mx0, __shfl_xor_sync(FULL, mx0, 1));
        mx0 = fmaxf(mx0, __shfl_xor_sync(FULL, mx0, 2));
        mx1 = fmaxf(mx1, __shfl_xor_sync(FULL, mx1, 1));
        mx1 = fmaxf(mx1, __shfl_xor_sync(FULL, mx1, 2));
        float nm0 = fmaxf(m0, mx0), nm1 = fmaxf(m1, mx1);
        float c0 = __expf(m0 - nm0), c1 = __expf(m1 - nm1);
        float s0 = 0.f, s1 = 0.f;
#pragma unroll
        for (int j = 0; j < 8; j++) {
            sf[j][0] = __expf(sf[j][0] - nm0);
            sf[j][1] = __expf(sf[j][1] - nm0);
            sf[j][2] = __expf(sf[j][2] - nm1);
            sf[j][3] = __expf(sf[j][3] - nm1);
            s0 += sf[j][0] + sf[j][1];
            s1 += sf[j][2] + sf[j][3];
        }
        s0 += __shfl_xor_sync(FULL, s0, 1);
        s0 += __shfl_xor_sync(FULL, s0, 2);
        s1 += __shfl_xor_sync(FULL, s1, 1);
        s1 += __shfl_xor_sync(FULL, s1, 2);
        l0 = l0 * c0 + s0; l1 = l1 * c1 + s1;
        m0 = nm0; m1 = nm1;
#pragma unroll
        for (int j = 0; j < 8; j++) {
            of[j][0] *= c0; of[j][1] *= c0;
            of[j][2] *= c1; of[j][3] *= c1;
        }

#pragma unroll
        for (int c = 0; c < 4; c++) {
            unsigned pah[4], pal[4];
            split2(sf[2*c][0],   sf[2*c][1],   pah[0], pal[0]);
            split2(sf[2*c][2],   sf[2*c][3],   pah[1], pal[1]);
            split2(sf[2*c+1][0], sf[2*c+1][1], pah[2], pal[2]);
            split2(sf[2*c+1][2], sf[2*c+1][3], pah[3], pal[3]);

            unsigned vf[8][2], tmp[4];
            unsigned vb = kb + (16*c + (lane & 7) + ((lane >> 3) & 1)*8)*PIT
                        + ((lane >> 4) & 1)*16;
#pragma unroll
            for (int g = 0; g < 4; g++) {
                ldsm4t(tmp, vb + AVH + g*32);
                vf[2*g][0]=tmp[0]; vf[2*g][1]=tmp[1];
                vf[2*g+1][0]=tmp[2]; vf[2*g+1][1]=tmp[3];
            }
#pragma unroll
            for (int nf = 0; nf < 8; nf++) {
                mma16816(of[nf], pah, vf[nf]);
                mma16816(of[nf], pal, vf[nf]);
            }
#pragma unroll
            for (int g = 0; g < 4; g++) {
                ldsm4t(tmp, vb + AVL + g*32);
                vf[2*g][0]=tmp[0]; vf[2*g][1]=tmp[1];
                vf[2*g+1][0]=tmp[2]; vf[2*g+1][1]=tmp[3];
            }
#pragma unroll
            for (int nf = 0; nf < 8; nf++)
                mma16816(of[nf], pah, vf[nf]);
        }
        __syncthreads();
    }

    float inv0 = 1.0f / l0, inv1 = 1.0f / l1;
    int q0 = qt*128 + wid*16 + (lane >> 2);
#pragma unroll
    for (int j = 0; j < 8; j++) {
        int d = h*HD + j*8 + 2*(lane & 3);
        unsigned hi, lo;
        size_t i0 = (size_t)(b*NN + q0) * CC + d;
        split2(of[j][0]*inv0, of[j][1]*inv0, hi, lo);
        *(unsigned*)&go_h[i0] = hi; *(unsigned*)&go_l[i0] = lo;
        size_t i1 = (size_t)(b*NN + q0 + 8) * CC + d;
        split2(of[j][2]*inv1, of[j][3]*inv1, hi, lo);
        *(unsigned*)&go_h[i1] = hi; *(unsigned*)&go_l[i1] = lo;
    }
}

// =============================================================================
extern "C" void kernel_launch(void* const* d_in, const int* in_sizes, int n_in,
                              void* d_out, int out_size) {
    const float* x     = (const float*)d_in[0];
    const float* mask  = (const float*)d_in[1];
    const float* Wqkv  = (const float*)d_in[2];
    const float* Wproj = (const float*)d_in[3];
    const float* bproj = (const float*)d_in[4];
    float* out = (float*)d_out;

    cudaFuncSetAttribute(mma_gemm<0>, cudaFuncAttributeMaxDynamicSharedMemorySize, GEMM_SMEM);
    cudaFuncSetAttribute(mma_gemm<1>, cudaFuncAttributeMaxDynamicSharedMemorySize, GEMM_SMEM);
    cudaFuncSetAttribute(attn_mma,    cudaFuncAttributeMaxDynamicSharedMemorySize, ATT_SMEM);

    int n4x = BB*NN*CC/4, n4q = 3*CC*CC/4, n4p = CC*CC/4;
    split_kernel<<<(n4x + 255)/256, 256>>>(x, 0, n4x);
    split_kernel<<<(n4q + 255)/256, 256>>>(Wqkv, 1, n4q);
    split_kernel<<<(n4p + 255)/256, 256>>>(Wproj, 2, n4p);

    dim3 g1(3*CC/128, BB*NN/128);     // (24, 128)
    mma_gemm<0><<<g1, 256, GEMM_SMEM>>>(nullptr, nullptr);

    dim3 g2(NN/128, HH, BB);          // (4, 16, 32)
    attn_mma<<<g2, 256, ATT_SMEM>>>(mask);

    dim3 g3(CC/128, BB*NN/128);       // (8, 128)
    mma_gemm<1><<<g3, 256, GEMM_SMEM>>>(bproj, out);
}